// round 13
// baseline (speedup 1.0000x reference)
#include <cuda_runtime.h>
#include <cuda_bf16.h>
#include <cstdint>

// ============================================================================
// BitLinear: y = (int8(x) @ ternary(W)^T) * (w_scale * a_scale / 127)
// Exact int8 IMMA (mma.sync m16n8k32 s8) GEMM, M=32768 N=1024 K=1024.
// Base sm_100 target: cp.async + mma.sync + ldmatrix.  No tcgen05/TMA.
// R13: B packed 4-bit (ternary fits a nibble) -> B L1 bytes halve
//      (56KB -> 40KB L1TEX per CTA-ktile; measured GEMM time tracks total
//      L1TEX bytes).  Decode = 4 masks + 1 mul on the idle ALU pipe.
//      Grid (4m x 2n), warp tile 32x64 (B-dominant config benefits most).
// ============================================================================

#define EPS_F 1e-8f

static constexpr int M_TOT = 32768;
static constexpr int N_TOT = 1024;
static constexpr int K_TOT = 1024;

static constexpr int BM = 128, BN = 128, BK = 64;
static constexpr int STAGES = 4;
static constexpr int KTILES = K_TOT / BK;            // 16
static constexpr int PITCH = 80;                     // 64B row padded to 80B
static constexpr int A_SM_BYTES = BM * PITCH;        // 10240
static constexpr int STAGE_BYTES = A_SM_BYTES;       // A only
static constexpr int SMEM_BYTES = STAGES * STAGE_BYTES; // 40960

// -------------------- device scratch (static; no allocations) ---------------
__device__ int8_t g_aq[(size_t)M_TOT * K_TOT];     // 32 MB
// B packed 4-bit in mma-fragment order: [ngrp(128)][kt(16)][ks(2)][lane(32)]
// u32 per lane: even nibbles = b0 codes (k..k+3), odd nibbles = b1 (k+16..+19)
// code = q & 0xF  (q in {-1,0,1} -> 0xF, 0, 1)
__device__ uint32_t g_bpack[128 * 16 * 2 * 32];     // 512 KB
__device__ float g_ascale[M_TOT];
__device__ float g_partial[1024];
__device__ float g_wscale;

// -------------------- PTX helpers -------------------------------------------
__device__ __forceinline__ uint32_t smem_u32(const void* p) {
    uint32_t a;
    asm("{ .reg .u64 t; cvta.to.shared.u64 t, %1; cvt.u32.u64 %0, t; }"
        : "=r"(a) : "l"(p));
    return a;
}

__device__ __forceinline__ void cpasync16(uint32_t dst, const void* src) {
    asm volatile("cp.async.cg.shared.global [%0], [%1], 16;"
                 :: "r"(dst), "l"(src) : "memory");
}

__device__ __forceinline__ void cp_commit() {
    asm volatile("cp.async.commit_group;" ::: "memory");
}

__device__ __forceinline__ void cp_wait2() {
    asm volatile("cp.async.wait_group 2;" ::: "memory");
}

__device__ __forceinline__ void ldsm4(uint32_t* r, uint32_t addr) {
    asm volatile("ldmatrix.sync.aligned.m8n8.x4.shared.b16 {%0,%1,%2,%3}, [%4];"
                 : "=r"(r[0]), "=r"(r[1]), "=r"(r[2]), "=r"(r[3]) : "r"(addr));
}

__device__ __forceinline__ void mma_s8(int* c, const uint32_t* a,
                                       uint32_t b0, uint32_t b1) {
    asm volatile(
        "mma.sync.aligned.m16n8k32.row.col.s32.s8.s8.s32 "
        "{%0,%1,%2,%3}, {%4,%5,%6,%7}, {%8,%9}, {%0,%1,%2,%3};"
        : "+r"(c[0]), "+r"(c[1]), "+r"(c[2]), "+r"(c[3])
        : "r"(a[0]), "r"(a[1]), "r"(a[2]), "r"(a[3]), "r"(b0), "r"(b1));
}

// nibble codes -> s8 bytes:  c in {0,1,0xF} -> byte {0x00,0x01,0xFF}
__device__ __forceinline__ uint32_t dec4(uint32_t c) {
    return c | (((c >> 3) & 0x01010101u) * 0xF0u);
}

// ============================================================================
// Kernel 1: per-block |W| partial sums (deterministic tree reduce)
// ============================================================================
__global__ void __launch_bounds__(256) wabs_kernel(const float* __restrict__ w) {
    __shared__ float sm[256];
    int t = threadIdx.x;
    size_t base = (size_t)blockIdx.x * 1024;
    float s = fabsf(w[base + t]) + fabsf(w[base + t + 256])
            + fabsf(w[base + t + 512]) + fabsf(w[base + t + 768]);
    sm[t] = s;
    __syncthreads();
    for (int o = 128; o > 0; o >>= 1) {
        if (t < o) sm[t] += sm[t + o];
        __syncthreads();
    }
    if (t == 0) g_partial[blockIdx.x] = sm[0];
}

// ============================================================================
// Kernel 2: ternary weight quant -> packed 4-bit B fragments.
// One output u32 per thread (8 weights).  Each block re-derives w_scale
// from the 1024 partials (deterministic); block 0 publishes it.
// ============================================================================
__global__ void __launch_bounds__(256) wquant_kernel(const float* __restrict__ w) {
    __shared__ float sm[256];
    int t = threadIdx.x;
    float s = g_partial[t] + g_partial[t + 256] + g_partial[t + 512] + g_partial[t + 768];
    sm[t] = s;
    __syncthreads();
    for (int o = 128; o > 0; o >>= 1) {
        if (t < o) sm[t] += sm[t + o];
        __syncthreads();
    }
    float ws = sm[0] / 1048576.0f + EPS_F;
    if (blockIdx.x == 0 && t == 0) g_wscale = ws;

    int oid = blockIdx.x * 256 + t;          // output u32 id, 131072 total
    int lane = oid & 31;
    int ks   = (oid >> 5) & 1;
    int kt   = (oid >> 6) & 15;
    int ngrp = oid >> 10;
    int r  = ngrp * 8 + (lane >> 2);
    int k0 = kt * 64 + ks * 32 + (lane & 3) * 4;
    const float* wr = w + (size_t)r * 1024 + k0;
    float4 v0 = *(const float4*)wr;          // b0 elements (k..k+3)
    float4 v1 = *(const float4*)(wr + 16);   // b1 elements (k+16..k+19)

    float inv = 1.0f / ws;
#define WCODE(f) ((uint32_t)(int)fminf(fmaxf(rintf((f) * inv), -1.0f), 1.0f) & 0xFu)
    uint32_t p = 0;
    p |= WCODE(v0.x) << 0;  p |= WCODE(v1.x) << 4;
    p |= WCODE(v0.y) << 8;  p |= WCODE(v1.y) << 12;
    p |= WCODE(v0.z) << 16; p |= WCODE(v1.z) << 20;
    p |= WCODE(v0.w) << 24; p |= WCODE(v1.w) << 28;
#undef WCODE
    g_bpack[oid] = p;
}

// ============================================================================
// Kernel 3: per-row activation quant -> int8.
// 128 threads per row (2 rows per 256-thread block).  __ldcs: x read-once.
// ============================================================================
__global__ void __launch_bounds__(256) xquant_kernel(const float* __restrict__ x) {
    __shared__ float red[8];
    int tid = threadIdx.x;
    int half = tid >> 7;
    int r = tid & 127;
    int row = blockIdx.x * 2 + half;
    const float4* xr = (const float4*)(x + (size_t)row * 1024);

    float4 v0 = __ldcs(xr + r);
    float4 v1 = __ldcs(xr + 128 + r);
    float m = fmaxf(fmaxf(fabsf(v0.x), fabsf(v0.y)), fmaxf(fabsf(v0.z), fabsf(v0.w)));
    m = fmaxf(m, fmaxf(fmaxf(fabsf(v1.x), fabsf(v1.y)),
                       fmaxf(fabsf(v1.z), fabsf(v1.w))));
#pragma unroll
    for (int o = 16; o; o >>= 1) m = fmaxf(m, __shfl_xor_sync(0xFFFFFFFFu, m, o));
    if ((tid & 31) == 0) red[tid >> 5] = m;
    __syncthreads();
    float mm = fmaxf(fmaxf(red[half * 4], red[half * 4 + 1]),
                     fmaxf(red[half * 4 + 2], red[half * 4 + 3]));
    float s = mm + EPS_F;
    if (r == 0) g_ascale[row] = s;

    float inv = 127.0f / s;
    uint32_t* q = (uint32_t*)(g_aq + (size_t)row * 1024);
    {
        int q0 = (int)rintf(fminf(fmaxf(v0.x * inv, -128.0f), 127.0f));
        int q1 = (int)rintf(fminf(fmaxf(v0.y * inv, -128.0f), 127.0f));
        int q2 = (int)rintf(fminf(fmaxf(v0.z * inv, -128.0f), 127.0f));
        int q3 = (int)rintf(fminf(fmaxf(v0.w * inv, -128.0f), 127.0f));
        q[r] = (uint32_t)(q0 & 0xFF) | ((uint32_t)(q1 & 0xFF) << 8)
             | ((uint32_t)(q2 & 0xFF) << 16) | ((uint32_t)(q3 & 0xFF) << 24);
    }
    {
        int q0 = (int)rintf(fminf(fmaxf(v1.x * inv, -128.0f), 127.0f));
        int q1 = (int)rintf(fminf(fmaxf(v1.y * inv, -128.0f), 127.0f));
        int q2 = (int)rintf(fminf(fmaxf(v1.z * inv, -128.0f), 127.0f));
        int q3 = (int)rintf(fminf(fmaxf(v1.w * inv, -128.0f), 127.0f));
        q[128 + r] = (uint32_t)(q0 & 0xFF) | ((uint32_t)(q1 & 0xFF) << 8)
                   | ((uint32_t)(q2 & 0xFF) << 16) | ((uint32_t)(q3 & 0xFF) << 24);
    }
}

// ============================================================================
// Kernel 4: int8 IMMA GEMM.  256 threads = 8 warps (4 m x 2 n),
// warp tile 32x64, CTA tile 128x128x64.  A: 4-stage cp.async + ldmatrix.
// B: packed 4-bit fragments via LDG.32 (L1/L2-resident), ALU decode.
// ============================================================================
__global__ void __launch_bounds__(256, 2)
gemm_kernel(float* __restrict__ out) {
    extern __shared__ __align__(16) char smem[];
    int tid = threadIdx.x;
    int wid = tid >> 5, lane = tid & 31;
    int wm = wid >> 1, wn = wid & 1;           // 4 m x 2 n warp grid
    int g = lane >> 2, q = lane & 3;
    int m0 = (int)(blockIdx.x >> 3) * BM;
    int n0 = (int)(blockIdx.x & 7) * BN;

    // A cp.async geometry: thread t -> row t/4, 16B chunk t%4 (x2 halves)
    int lrow = tid >> 2, lcol = tid & 3;
    const int8_t* asrc0 = g_aq + (size_t)(m0 + lrow) * K_TOT + lcol * 16;
    uint32_t sbase = smem_u32(smem);
    uint32_t adst0 = sbase + lrow * PITCH + lcol * 16;

    // A ldmatrix per-lane address (within stage 0): warp rows wm*32..+31
    uint32_t a_lm = sbase
        + (uint32_t)(wm * 32 + (lane & 7) + ((lane >> 3) & 1) * 8) * PITCH
        + ((lane >> 4) & 1) * 16;

    // B packed pointer: warp covers n-groups (n0/8 + wn*8) .. +7.
    // ngrp stride in u32 = 16*2*32 = 1024.
    const uint32_t* bwp = g_bpack + (size_t)((n0 >> 3) + wn * 8) * 1024 + lane;

    int acc[2][8][4];
#pragma unroll
    for (int i = 0; i < 2; i++)
#pragma unroll
        for (int j = 0; j < 8; j++)
#pragma unroll
            for (int r = 0; r < 4; r++) acc[i][j][r] = 0;

    // ---- prologue: fill first STAGES-1 stages (A only) ----
#pragma unroll
    for (int s = 0; s < STAGES - 1; s++) {
        uint32_t so = (uint32_t)s * STAGE_BYTES;
        cpasync16(adst0 + so, asrc0 + s * BK);
        cpasync16(adst0 + so + 64 * PITCH, asrc0 + (size_t)64 * K_TOT + s * BK);
        cp_commit();
    }

#pragma unroll 1
    for (int kt = 0; kt < KTILES; kt++) {
        // B packed loads for this k-tile, issued BEFORE the pipeline wait
        // so their L2 latency hides behind it.  bvp[nb*2+ks].
        uint32_t bvp[16];
#pragma unroll
        for (int nb = 0; nb < 8; nb++) {
            bvp[nb * 2 + 0] = __ldg(bwp + nb * 1024 + kt * 64);
            bvp[nb * 2 + 1] = __ldg(bwp + nb * 1024 + kt * 64 + 32);
        }

        cp_wait2();
        __syncthreads();

        int pf = kt + STAGES - 1;
        if (pf < KTILES) {
            uint32_t so = (uint32_t)(pf & (STAGES - 1)) * STAGE_BYTES;
            cpasync16(adst0 + so, asrc0 + pf * BK);
            cpasync16(adst0 + so + 64 * PITCH, asrc0 + (size_t)64 * K_TOT + pf * BK);
        }
        cp_commit();

        uint32_t As = a_lm + (uint32_t)(kt & (STAGES - 1)) * STAGE_BYTES;

#pragma unroll
        for (int ks = 0; ks < 2; ks++) {
            uint32_t a[2][4];
#pragma unroll
            for (int mb = 0; mb < 2; mb++)
                ldsm4(a[mb], As + mb * (16 * PITCH) + ks * 32);
#pragma unroll
            for (int nb = 0; nb < 8; nb++) {
                uint32_t p  = bvp[nb * 2 + ks];
                uint32_t b0 = dec4(p & 0x0F0F0F0Fu);
                uint32_t b1 = dec4((p >> 4) & 0x0F0F0F0Fu);
#pragma unroll
                for (int mb = 0; mb < 2; mb++)
                    mma_s8(acc[mb][nb], a[mb], b0, b1);
            }
        }
    }

    // ---- epilogue: dequant rescale + float2 stores ----
    float wsc = g_wscale * (1.0f / 127.0f);
#pragma unroll
    for (int mb = 0; mb < 2; mb++) {
        int r0 = m0 + wm * 32 + mb * 16 + g;
        float sc0 = wsc * g_ascale[r0];
        float sc1 = wsc * g_ascale[r0 + 8];
        float* o0 = out + (size_t)r0 * N_TOT + n0 + wn * 64 + q * 2;
        float* o1 = o0 + (size_t)8 * N_TOT;
#pragma unroll
        for (int nb = 0; nb < 8; nb++) {
            float2 v0, v1;
            v0.x = (float)acc[mb][nb][0] * sc0;
            v0.y = (float)acc[mb][nb][1] * sc0;
            v1.x = (float)acc[mb][nb][2] * sc1;
            v1.y = (float)acc[mb][nb][3] * sc1;
            *(float2*)(o0 + nb * 8) = v0;
            *(float2*)(o1 + nb * 8) = v1;
        }
    }
}

// ============================================================================
// Host launch
// ============================================================================
extern "C" void kernel_launch(void* const* d_in, const int* in_sizes, int n_in,
                              void* d_out, int out_size) {
    (void)in_sizes; (void)n_in; (void)out_size;
    const float* x = (const float*)d_in[0];
    const float* w = (const float*)d_in[1];
    float* out = (float*)d_out;

    cudaFuncSetAttribute(gemm_kernel, cudaFuncAttributeMaxDynamicSharedMemorySize,
                         SMEM_BYTES);

    wabs_kernel<<<1024, 256>>>(w);
    wquant_kernel<<<512, 256>>>(w);
    xquant_kernel<<<M_TOT / 2, 256>>>(x);
    gemm_kernel<<<(M_TOT / BM) * (N_TOT / BN), 256, SMEM_BYTES>>>(out);
}

// round 14
// speedup vs baseline: 1.1308x; 1.1308x over previous
#include <cuda_runtime.h>
#include <cuda_bf16.h>
#include <cstdint>

// ============================================================================
// BitLinear: y = (int8(x) @ ternary(W)^T) * (w_scale * a_scale / 127)
// Exact int8 IMMA (mma.sync m16n8k32 s8) GEMM, M=32768 N=1024 K=1024.
// Base sm_100 target: cp.async + mma.sync + ldmatrix.  No tcgen05/TMA.
// R14: 4-bit B kept (L1 win from R13) but decode via single PRMT per
//      fragment (code = q+1 in nibbles; LUT 0x000100FF).  Decode cost
//      112 -> 48 issue slots per warp-ktile (R13's regression cause:
//      ALU 42%/issue 42%).  Grid (4m x 2n), warp tile 32x64.
// ============================================================================

#define EPS_F 1e-8f

static constexpr int M_TOT = 32768;
static constexpr int N_TOT = 1024;
static constexpr int K_TOT = 1024;

static constexpr int BM = 128, BN = 128, BK = 64;
static constexpr int STAGES = 4;
static constexpr int KTILES = K_TOT / BK;            // 16
static constexpr int PITCH = 80;                     // 64B row padded to 80B
static constexpr int A_SM_BYTES = BM * PITCH;        // 10240
static constexpr int STAGE_BYTES = A_SM_BYTES;       // A only
static constexpr int SMEM_BYTES = STAGES * STAGE_BYTES; // 40960

// -------------------- device scratch (static; no allocations) ---------------
__device__ int8_t g_aq[(size_t)M_TOT * K_TOT];     // 32 MB
// B packed as PRMT selectors in mma-fragment order:
// [ngrp(128)][kt(16)][ks(2)][lane(32)] u32.
// bits[15:0]  = 4 nibble codes for b0 bytes (k..k+3),  code = q+1 in {0,1,2}
// bits[31:16] = 4 nibble codes for b1 bytes (k+16..k+19)
__device__ uint32_t g_bpack[128 * 16 * 2 * 32];     // 512 KB
__device__ float g_ascale[M_TOT];
__device__ float g_partial[1024];
__device__ float g_wscale;

// -------------------- PTX helpers -------------------------------------------
__device__ __forceinline__ uint32_t smem_u32(const void* p) {
    uint32_t a;
    asm("{ .reg .u64 t; cvta.to.shared.u64 t, %1; cvt.u32.u64 %0, t; }"
        : "=r"(a) : "l"(p));
    return a;
}

__device__ __forceinline__ void cpasync16(uint32_t dst, const void* src) {
    asm volatile("cp.async.cg.shared.global [%0], [%1], 16;"
                 :: "r"(dst), "l"(src) : "memory");
}

__device__ __forceinline__ void cp_commit() {
    asm volatile("cp.async.commit_group;" ::: "memory");
}

__device__ __forceinline__ void cp_wait2() {
    asm volatile("cp.async.wait_group 2;" ::: "memory");
}

__device__ __forceinline__ void ldsm4(uint32_t* r, uint32_t addr) {
    asm volatile("ldmatrix.sync.aligned.m8n8.x4.shared.b16 {%0,%1,%2,%3}, [%4];"
                 : "=r"(r[0]), "=r"(r[1]), "=r"(r[2]), "=r"(r[3]) : "r"(addr));
}

__device__ __forceinline__ void mma_s8(int* c, const uint32_t* a,
                                       uint32_t b0, uint32_t b1) {
    asm volatile(
        "mma.sync.aligned.m16n8k32.row.col.s32.s8.s8.s32 "
        "{%0,%1,%2,%3}, {%4,%5,%6,%7}, {%8,%9}, {%0,%1,%2,%3};"
        : "+r"(c[0]), "+r"(c[1]), "+r"(c[2]), "+r"(c[3])
        : "r"(a[0]), "r"(a[1]), "r"(a[2]), "r"(a[3]), "r"(b0), "r"(b1));
}

// PRMT decode: selector nibbles in {0,1,2} pick bytes {0xFF,0x00,0x01}
__device__ __forceinline__ uint32_t prmt_dec(uint32_t sel) {
    uint32_t d;
    asm("prmt.b32 %0, %1, %2, %3;"
        : "=r"(d) : "r"(0x000100FFu), "r"(0u), "r"(sel));
    return d;
}

// ============================================================================
// Kernel 1: per-block |W| partial sums (deterministic tree reduce)
// ============================================================================
__global__ void __launch_bounds__(256) wabs_kernel(const float* __restrict__ w) {
    __shared__ float sm[256];
    int t = threadIdx.x;
    size_t base = (size_t)blockIdx.x * 1024;
    float s = fabsf(w[base + t]) + fabsf(w[base + t + 256])
            + fabsf(w[base + t + 512]) + fabsf(w[base + t + 768]);
    sm[t] = s;
    __syncthreads();
    for (int o = 128; o > 0; o >>= 1) {
        if (t < o) sm[t] += sm[t + o];
        __syncthreads();
    }
    if (t == 0) g_partial[blockIdx.x] = sm[0];
}

// ============================================================================
// Kernel 2: ternary weight quant -> PRMT-selector fragments.
// One output u32 per thread (8 weights).  Each block re-derives w_scale
// from the 1024 partials (deterministic); block 0 publishes it.
// ============================================================================
__global__ void __launch_bounds__(256) wquant_kernel(const float* __restrict__ w) {
    __shared__ float sm[256];
    int t = threadIdx.x;
    float s = g_partial[t] + g_partial[t + 256] + g_partial[t + 512] + g_partial[t + 768];
    sm[t] = s;
    __syncthreads();
    for (int o = 128; o > 0; o >>= 1) {
        if (t < o) sm[t] += sm[t + o];
        __syncthreads();
    }
    float ws = sm[0] / 1048576.0f + EPS_F;
    if (blockIdx.x == 0 && t == 0) g_wscale = ws;

    int oid = blockIdx.x * 256 + t;          // output u32 id, 131072 total
    int lane = oid & 31;
    int ks   = (oid >> 5) & 1;
    int kt   = (oid >> 6) & 15;
    int ngrp = oid >> 10;
    int r  = ngrp * 8 + (lane >> 2);
    int k0 = kt * 64 + ks * 32 + (lane & 3) * 4;
    const float* wr = w + (size_t)r * 1024 + k0;
    float4 v0 = *(const float4*)wr;          // b0 elements (k..k+3)
    float4 v1 = *(const float4*)(wr + 16);   // b1 elements (k+16..k+19)

    float inv = 1.0f / ws;
    // code = clamp(round(w/ws),-1,1) + 1  in {0,1,2}
#define WCODE(f) ((uint32_t)((int)fminf(fmaxf(rintf((f) * inv), -1.0f), 1.0f) + 1))
    uint32_t p = 0;
    p |= WCODE(v0.x) << 0;  p |= WCODE(v0.y) << 4;
    p |= WCODE(v0.z) << 8;  p |= WCODE(v0.w) << 12;
    p |= WCODE(v1.x) << 16; p |= WCODE(v1.y) << 20;
    p |= WCODE(v1.z) << 24; p |= WCODE(v1.w) << 28;
#undef WCODE
    g_bpack[oid] = p;
}

// ============================================================================
// Kernel 3: per-row activation quant -> int8.
// 128 threads per row (2 rows per 256-thread block).  __ldcs: x read-once.
// ============================================================================
__global__ void __launch_bounds__(256) xquant_kernel(const float* __restrict__ x) {
    __shared__ float red[8];
    int tid = threadIdx.x;
    int half = tid >> 7;
    int r = tid & 127;
    int row = blockIdx.x * 2 + half;
    const float4* xr = (const float4*)(x + (size_t)row * 1024);

    float4 v0 = __ldcs(xr + r);
    float4 v1 = __ldcs(xr + 128 + r);
    float m = fmaxf(fmaxf(fabsf(v0.x), fabsf(v0.y)), fmaxf(fabsf(v0.z), fabsf(v0.w)));
    m = fmaxf(m, fmaxf(fmaxf(fabsf(v1.x), fabsf(v1.y)),
                       fmaxf(fabsf(v1.z), fabsf(v1.w))));
#pragma unroll
    for (int o = 16; o; o >>= 1) m = fmaxf(m, __shfl_xor_sync(0xFFFFFFFFu, m, o));
    if ((tid & 31) == 0) red[tid >> 5] = m;
    __syncthreads();
    float mm = fmaxf(fmaxf(red[half * 4], red[half * 4 + 1]),
                     fmaxf(red[half * 4 + 2], red[half * 4 + 3]));
    float s = mm + EPS_F;
    if (r == 0) g_ascale[row] = s;

    float inv = 127.0f / s;
    uint32_t* q = (uint32_t*)(g_aq + (size_t)row * 1024);
    {
        int q0 = (int)rintf(fminf(fmaxf(v0.x * inv, -128.0f), 127.0f));
        int q1 = (int)rintf(fminf(fmaxf(v0.y * inv, -128.0f), 127.0f));
        int q2 = (int)rintf(fminf(fmaxf(v0.z * inv, -128.0f), 127.0f));
        int q3 = (int)rintf(fminf(fmaxf(v0.w * inv, -128.0f), 127.0f));
        q[r] = (uint32_t)(q0 & 0xFF) | ((uint32_t)(q1 & 0xFF) << 8)
             | ((uint32_t)(q2 & 0xFF) << 16) | ((uint32_t)(q3 & 0xFF) << 24);
    }
    {
        int q0 = (int)rintf(fminf(fmaxf(v1.x * inv, -128.0f), 127.0f));
        int q1 = (int)rintf(fminf(fmaxf(v1.y * inv, -128.0f), 127.0f));
        int q2 = (int)rintf(fminf(fmaxf(v1.z * inv, -128.0f), 127.0f));
        int q3 = (int)rintf(fminf(fmaxf(v1.w * inv, -128.0f), 127.0f));
        q[128 + r] = (uint32_t)(q0 & 0xFF) | ((uint32_t)(q1 & 0xFF) << 8)
                   | ((uint32_t)(q2 & 0xFF) << 16) | ((uint32_t)(q3 & 0xFF) << 24);
    }
}

// ============================================================================
// Kernel 4: int8 IMMA GEMM.  256 threads = 8 warps (4 m x 2 n),
// warp tile 32x64, CTA tile 128x128x64.  A: 4-stage cp.async + ldmatrix.
// B: 4-bit PRMT-selector fragments via LDG.32, 1 PRMT per fragment decode.
// ============================================================================
__global__ void __launch_bounds__(256, 2)
gemm_kernel(float* __restrict__ out) {
    extern __shared__ __align__(16) char smem[];
    int tid = threadIdx.x;
    int wid = tid >> 5, lane = tid & 31;
    int wm = wid >> 1, wn = wid & 1;           // 4 m x 2 n warp grid
    int g = lane >> 2, q = lane & 3;
    int m0 = (int)(blockIdx.x >> 3) * BM;
    int n0 = (int)(blockIdx.x & 7) * BN;

    // A cp.async geometry: thread t -> row t/4, 16B chunk t%4 (x2 halves)
    int lrow = tid >> 2, lcol = tid & 3;
    const int8_t* asrc0 = g_aq + (size_t)(m0 + lrow) * K_TOT + lcol * 16;
    uint32_t sbase = smem_u32(smem);
    uint32_t adst0 = sbase + lrow * PITCH + lcol * 16;

    // A ldmatrix per-lane address (within stage 0): warp rows wm*32..+31
    uint32_t a_lm = sbase
        + (uint32_t)(wm * 32 + (lane & 7) + ((lane >> 3) & 1) * 8) * PITCH
        + ((lane >> 4) & 1) * 16;

    // B packed pointer: warp covers n-groups (n0/8 + wn*8) .. +7.
    // ngrp stride in u32 = 16*2*32 = 1024.
    const uint32_t* bwp = g_bpack + (size_t)((n0 >> 3) + wn * 8) * 1024 + lane;

    int acc[2][8][4];
#pragma unroll
    for (int i = 0; i < 2; i++)
#pragma unroll
        for (int j = 0; j < 8; j++)
#pragma unroll
            for (int r = 0; r < 4; r++) acc[i][j][r] = 0;

    // ---- prologue: fill first STAGES-1 stages (A only) ----
#pragma unroll
    for (int s = 0; s < STAGES - 1; s++) {
        uint32_t so = (uint32_t)s * STAGE_BYTES;
        cpasync16(adst0 + so, asrc0 + s * BK);
        cpasync16(adst0 + so + 64 * PITCH, asrc0 + (size_t)64 * K_TOT + s * BK);
        cp_commit();
    }

#pragma unroll 1
    for (int kt = 0; kt < KTILES; kt++) {
        // B packed loads for this k-tile, issued BEFORE the pipeline wait
        // so their L2 latency hides behind it.  bvp[nb*2+ks].
        uint32_t bvp[16];
#pragma unroll
        for (int nb = 0; nb < 8; nb++) {
            bvp[nb * 2 + 0] = __ldg(bwp + nb * 1024 + kt * 64);
            bvp[nb * 2 + 1] = __ldg(bwp + nb * 1024 + kt * 64 + 32);
        }

        cp_wait2();
        __syncthreads();

        int pf = kt + STAGES - 1;
        if (pf < KTILES) {
            uint32_t so = (uint32_t)(pf & (STAGES - 1)) * STAGE_BYTES;
            cpasync16(adst0 + so, asrc0 + pf * BK);
            cpasync16(adst0 + so + 64 * PITCH, asrc0 + (size_t)64 * K_TOT + pf * BK);
        }
        cp_commit();

        uint32_t As = a_lm + (uint32_t)(kt & (STAGES - 1)) * STAGE_BYTES;

#pragma unroll
        for (int ks = 0; ks < 2; ks++) {
            uint32_t a[2][4];
#pragma unroll
            for (int mb = 0; mb < 2; mb++)
                ldsm4(a[mb], As + mb * (16 * PITCH) + ks * 32);
#pragma unroll
            for (int nb = 0; nb < 8; nb++) {
                uint32_t p  = bvp[nb * 2 + ks];
                uint32_t b0 = prmt_dec(p);          // low 16 bits
                uint32_t b1 = prmt_dec(p >> 16);    // high 16 bits
#pragma unroll
                for (int mb = 0; mb < 2; mb++)
                    mma_s8(acc[mb][nb], a[mb], b0, b1);
            }
        }
    }

    // ---- epilogue: dequant rescale + float2 stores ----
    float wsc = g_wscale * (1.0f / 127.0f);
#pragma unroll
    for (int mb = 0; mb < 2; mb++) {
        int r0 = m0 + wm * 32 + mb * 16 + g;
        float sc0 = wsc * g_ascale[r0];
        float sc1 = wsc * g_ascale[r0 + 8];
        float* o0 = out + (size_t)r0 * N_TOT + n0 + wn * 64 + q * 2;
        float* o1 = o0 + (size_t)8 * N_TOT;
#pragma unroll
        for (int nb = 0; nb < 8; nb++) {
            float2 v0, v1;
            v0.x = (float)acc[mb][nb][0] * sc0;
            v0.y = (float)acc[mb][nb][1] * sc0;
            v1.x = (float)acc[mb][nb][2] * sc1;
            v1.y = (float)acc[mb][nb][3] * sc1;
            *(float2*)(o0 + nb * 8) = v0;
            *(float2*)(o1 + nb * 8) = v1;
        }
    }
}

// ============================================================================
// Host launch
// ============================================================================
extern "C" void kernel_launch(void* const* d_in, const int* in_sizes, int n_in,
                              void* d_out, int out_size) {
    (void)in_sizes; (void)n_in; (void)out_size;
    const float* x = (const float*)d_in[0];
    const float* w = (const float*)d_in[1];
    float* out = (float*)d_out;

    cudaFuncSetAttribute(gemm_kernel, cudaFuncAttributeMaxDynamicSharedMemorySize,
                         SMEM_BYTES);

    wabs_kernel<<<1024, 256>>>(w);
    wquant_kernel<<<512, 256>>>(w);
    xquant_kernel<<<M_TOT / 2, 256>>>(x);
    gemm_kernel<<<(M_TOT / BM) * (N_TOT / BN), 256, SMEM_BYTES>>>(out);
}

// round 15
// speedup vs baseline: 1.1938x; 1.0558x over previous
#include <cuda_runtime.h>
#include <cuda_bf16.h>
#include <cstdint>

// ============================================================================
// BitLinear: y = (int8(x) @ ternary(W)^T) * (w_scale * a_scale / 127)
// Exact int8 IMMA (mma.sync m16n8k32 s8) GEMM, M=32768 N=1024 K=1024.
// Base sm_100 target: cp.async + mma.sync + ldmatrix.  No tcgen05/TMA.
// R15: 4-bit PRMT B (R14) paired with the B-LIGHT warp grid (2m x 4n,
//      warp tile 64x32 = R11 geometry).  L1 bytes/CTA-ktile 56->48 KB and
//      decode ops halve vs R14 (nb=4 not 8).  Both terms dominate all
//      measured configs.
// ============================================================================

#define EPS_F 1e-8f

static constexpr int M_TOT = 32768;
static constexpr int N_TOT = 1024;
static constexpr int K_TOT = 1024;

static constexpr int BM = 128, BN = 128, BK = 64;
static constexpr int STAGES = 4;
static constexpr int KTILES = K_TOT / BK;            // 16
static constexpr int PITCH = 80;                     // 64B row padded to 80B
static constexpr int A_SM_BYTES = BM * PITCH;        // 10240
static constexpr int STAGE_BYTES = A_SM_BYTES;       // A only
static constexpr int SMEM_BYTES = STAGES * STAGE_BYTES; // 40960

// -------------------- device scratch (static; no allocations) ---------------
__device__ int8_t g_aq[(size_t)M_TOT * K_TOT];     // 32 MB
// B packed as PRMT selectors in mma-fragment order:
// [ngrp(128)][kt(16)][ks(2)][lane(32)] u32.
// bits[15:0]  = 4 nibble codes for b0 bytes (k..k+3),  code = q+1 in {0,1,2}
// bits[31:16] = 4 nibble codes for b1 bytes (k+16..k+19)
__device__ uint32_t g_bpack[128 * 16 * 2 * 32];     // 512 KB
__device__ float g_ascale[M_TOT];
__device__ float g_partial[1024];
__device__ float g_wscale;

// -------------------- PTX helpers -------------------------------------------
__device__ __forceinline__ uint32_t smem_u32(const void* p) {
    uint32_t a;
    asm("{ .reg .u64 t; cvta.to.shared.u64 t, %1; cvt.u32.u64 %0, t; }"
        : "=r"(a) : "l"(p));
    return a;
}

__device__ __forceinline__ void cpasync16(uint32_t dst, const void* src) {
    asm volatile("cp.async.cg.shared.global [%0], [%1], 16;"
                 :: "r"(dst), "l"(src) : "memory");
}

__device__ __forceinline__ void cp_commit() {
    asm volatile("cp.async.commit_group;" ::: "memory");
}

__device__ __forceinline__ void cp_wait2() {
    asm volatile("cp.async.wait_group 2;" ::: "memory");
}

__device__ __forceinline__ void ldsm4(uint32_t* r, uint32_t addr) {
    asm volatile("ldmatrix.sync.aligned.m8n8.x4.shared.b16 {%0,%1,%2,%3}, [%4];"
                 : "=r"(r[0]), "=r"(r[1]), "=r"(r[2]), "=r"(r[3]) : "r"(addr));
}

__device__ __forceinline__ void mma_s8(int* c, const uint32_t* a,
                                       uint32_t b0, uint32_t b1) {
    asm volatile(
        "mma.sync.aligned.m16n8k32.row.col.s32.s8.s8.s32 "
        "{%0,%1,%2,%3}, {%4,%5,%6,%7}, {%8,%9}, {%0,%1,%2,%3};"
        : "+r"(c[0]), "+r"(c[1]), "+r"(c[2]), "+r"(c[3])
        : "r"(a[0]), "r"(a[1]), "r"(a[2]), "r"(a[3]), "r"(b0), "r"(b1));
}

// PRMT decode: selector nibbles in {0,1,2} pick bytes {0xFF,0x00,0x01}
__device__ __forceinline__ uint32_t prmt_dec(uint32_t sel) {
    uint32_t d;
    asm("prmt.b32 %0, %1, %2, %3;"
        : "=r"(d) : "r"(0x000100FFu), "r"(0u), "r"(sel));
    return d;
}

// ============================================================================
// Kernel 1: per-block |W| partial sums (deterministic tree reduce)
// ============================================================================
__global__ void __launch_bounds__(256) wabs_kernel(const float* __restrict__ w) {
    __shared__ float sm[256];
    int t = threadIdx.x;
    size_t base = (size_t)blockIdx.x * 1024;
    float s = fabsf(w[base + t]) + fabsf(w[base + t + 256])
            + fabsf(w[base + t + 512]) + fabsf(w[base + t + 768]);
    sm[t] = s;
    __syncthreads();
    for (int o = 128; o > 0; o >>= 1) {
        if (t < o) sm[t] += sm[t + o];
        __syncthreads();
    }
    if (t == 0) g_partial[blockIdx.x] = sm[0];
}

// ============================================================================
// Kernel 2: ternary weight quant -> PRMT-selector fragments.
// One output u32 per thread (8 weights).  Each block re-derives w_scale
// from the 1024 partials (deterministic); block 0 publishes it.
// ============================================================================
__global__ void __launch_bounds__(256) wquant_kernel(const float* __restrict__ w) {
    __shared__ float sm[256];
    int t = threadIdx.x;
    float s = g_partial[t] + g_partial[t + 256] + g_partial[t + 512] + g_partial[t + 768];
    sm[t] = s;
    __syncthreads();
    for (int o = 128; o > 0; o >>= 1) {
        if (t < o) sm[t] += sm[t + o];
        __syncthreads();
    }
    float ws = sm[0] / 1048576.0f + EPS_F;
    if (blockIdx.x == 0 && t == 0) g_wscale = ws;

    int oid = blockIdx.x * 256 + t;          // output u32 id, 131072 total
    int lane = oid & 31;
    int ks   = (oid >> 5) & 1;
    int kt   = (oid >> 6) & 15;
    int ngrp = oid >> 10;
    int r  = ngrp * 8 + (lane >> 2);
    int k0 = kt * 64 + ks * 32 + (lane & 3) * 4;
    const float* wr = w + (size_t)r * 1024 + k0;
    float4 v0 = *(const float4*)wr;          // b0 elements (k..k+3)
    float4 v1 = *(const float4*)(wr + 16);   // b1 elements (k+16..k+19)

    float inv = 1.0f / ws;
    // code = clamp(round(w/ws),-1,1) + 1  in {0,1,2}
#define WCODE(f) ((uint32_t)((int)fminf(fmaxf(rintf((f) * inv), -1.0f), 1.0f) + 1))
    uint32_t p = 0;
    p |= WCODE(v0.x) << 0;  p |= WCODE(v0.y) << 4;
    p |= WCODE(v0.z) << 8;  p |= WCODE(v0.w) << 12;
    p |= WCODE(v1.x) << 16; p |= WCODE(v1.y) << 20;
    p |= WCODE(v1.z) << 24; p |= WCODE(v1.w) << 28;
#undef WCODE
    g_bpack[oid] = p;
}

// ============================================================================
// Kernel 3: per-row activation quant -> int8.
// 128 threads per row (2 rows per 256-thread block).  __ldcs: x read-once.
// ============================================================================
__global__ void __launch_bounds__(256) xquant_kernel(const float* __restrict__ x) {
    __shared__ float red[8];
    int tid = threadIdx.x;
    int half = tid >> 7;
    int r = tid & 127;
    int row = blockIdx.x * 2 + half;
    const float4* xr = (const float4*)(x + (size_t)row * 1024);

    float4 v0 = __ldcs(xr + r);
    float4 v1 = __ldcs(xr + 128 + r);
    float m = fmaxf(fmaxf(fabsf(v0.x), fabsf(v0.y)), fmaxf(fabsf(v0.z), fabsf(v0.w)));
    m = fmaxf(m, fmaxf(fmaxf(fabsf(v1.x), fabsf(v1.y)),
                       fmaxf(fabsf(v1.z), fabsf(v1.w))));
#pragma unroll
    for (int o = 16; o; o >>= 1) m = fmaxf(m, __shfl_xor_sync(0xFFFFFFFFu, m, o));
    if ((tid & 31) == 0) red[tid >> 5] = m;
    __syncthreads();
    float mm = fmaxf(fmaxf(red[half * 4], red[half * 4 + 1]),
                     fmaxf(red[half * 4 + 2], red[half * 4 + 3]));
    float s = mm + EPS_F;
    if (r == 0) g_ascale[row] = s;

    float inv = 127.0f / s;
    uint32_t* q = (uint32_t*)(g_aq + (size_t)row * 1024);
    {
        int q0 = (int)rintf(fminf(fmaxf(v0.x * inv, -128.0f), 127.0f));
        int q1 = (int)rintf(fminf(fmaxf(v0.y * inv, -128.0f), 127.0f));
        int q2 = (int)rintf(fminf(fmaxf(v0.z * inv, -128.0f), 127.0f));
        int q3 = (int)rintf(fminf(fmaxf(v0.w * inv, -128.0f), 127.0f));
        q[r] = (uint32_t)(q0 & 0xFF) | ((uint32_t)(q1 & 0xFF) << 8)
             | ((uint32_t)(q2 & 0xFF) << 16) | ((uint32_t)(q3 & 0xFF) << 24);
    }
    {
        int q0 = (int)rintf(fminf(fmaxf(v1.x * inv, -128.0f), 127.0f));
        int q1 = (int)rintf(fminf(fmaxf(v1.y * inv, -128.0f), 127.0f));
        int q2 = (int)rintf(fminf(fmaxf(v1.z * inv, -128.0f), 127.0f));
        int q3 = (int)rintf(fminf(fmaxf(v1.w * inv, -128.0f), 127.0f));
        q[128 + r] = (uint32_t)(q0 & 0xFF) | ((uint32_t)(q1 & 0xFF) << 8)
                   | ((uint32_t)(q2 & 0xFF) << 16) | ((uint32_t)(q3 & 0xFF) << 24);
    }
}

// ============================================================================
// Kernel 4: int8 IMMA GEMM.  256 threads = 8 warps (2 m x 4 n),
// warp tile 64x32, CTA tile 128x128x64.  A: 4-stage cp.async + ldmatrix.
// B: 4-bit PRMT-selector fragments via LDG.32, 1 shift + 2 PRMT per
// (nb,ks) decode — only 4 nb per warp in this grid.
// ============================================================================
__global__ void __launch_bounds__(256, 2)
gemm_kernel(float* __restrict__ out) {
    extern __shared__ __align__(16) char smem[];
    int tid = threadIdx.x;
    int wid = tid >> 5, lane = tid & 31;
    int wm = wid >> 2, wn = wid & 3;           // 2 m x 4 n warp grid
    int g = lane >> 2, q = lane & 3;
    int m0 = (int)(blockIdx.x >> 3) * BM;
    int n0 = (int)(blockIdx.x & 7) * BN;

    // A cp.async geometry: thread t -> row t/4, 16B chunk t%4 (x2 halves)
    int lrow = tid >> 2, lcol = tid & 3;
    const int8_t* asrc0 = g_aq + (size_t)(m0 + lrow) * K_TOT + lcol * 16;
    uint32_t sbase = smem_u32(smem);
    uint32_t adst0 = sbase + lrow * PITCH + lcol * 16;

    // A ldmatrix per-lane address (within stage 0): warp rows wm*64..+63
    uint32_t a_lm = sbase
        + (uint32_t)(wm * 64 + (lane & 7) + ((lane >> 3) & 1) * 8) * PITCH
        + ((lane >> 4) & 1) * 16;

    // B packed pointer: warp covers n-groups (n0/8 + wn*4) .. +3.
    // ngrp stride in u32 = 16*2*32 = 1024.
    const uint32_t* bwp = g_bpack + (size_t)((n0 >> 3) + wn * 4) * 1024 + lane;

    int acc[4][4][4];
#pragma unroll
    for (int i = 0; i < 4; i++)
#pragma unroll
        for (int j = 0; j < 4; j++)
#pragma unroll
            for (int r = 0; r < 4; r++) acc[i][j][r] = 0;

    // ---- prologue: fill first STAGES-1 stages (A only) ----
#pragma unroll
    for (int s = 0; s < STAGES - 1; s++) {
        uint32_t so = (uint32_t)s * STAGE_BYTES;
        cpasync16(adst0 + so, asrc0 + s * BK);
        cpasync16(adst0 + so + 64 * PITCH, asrc0 + (size_t)64 * K_TOT + s * BK);
        cp_commit();
    }

#pragma unroll 1
    for (int kt = 0; kt < KTILES; kt++) {
        // B packed loads for this k-tile, issued BEFORE the pipeline wait
        // so their L2 latency hides behind it.  bvp[nb*2+ks].
        uint32_t bvp[8];
#pragma unroll
        for (int nb = 0; nb < 4; nb++) {
            bvp[nb * 2 + 0] = __ldg(bwp + nb * 1024 + kt * 64);
            bvp[nb * 2 + 1] = __ldg(bwp + nb * 1024 + kt * 64 + 32);
        }

        cp_wait2();
        __syncthreads();

        int pf = kt + STAGES - 1;
        if (pf < KTILES) {
            uint32_t so = (uint32_t)(pf & (STAGES - 1)) * STAGE_BYTES;
            cpasync16(adst0 + so, asrc0 + pf * BK);
            cpasync16(adst0 + so + 64 * PITCH, asrc0 + (size_t)64 * K_TOT + pf * BK);
        }
        cp_commit();

        uint32_t As = a_lm + (uint32_t)(kt & (STAGES - 1)) * STAGE_BYTES;

#pragma unroll
        for (int ks = 0; ks < 2; ks++) {
            uint32_t a[4][4];
#pragma unroll
            for (int mb = 0; mb < 4; mb++)
                ldsm4(a[mb], As + mb * (16 * PITCH) + ks * 32);
#pragma unroll
            for (int nb = 0; nb < 4; nb++) {
                uint32_t p  = bvp[nb * 2 + ks];
                uint32_t b0 = prmt_dec(p);          // low 16 bits
                uint32_t b1 = prmt_dec(p >> 16);    // high 16 bits
#pragma unroll
                for (int mb = 0; mb < 4; mb++)
                    mma_s8(acc[mb][nb], a[mb], b0, b1);
            }
        }
    }

    // ---- epilogue: dequant rescale + float2 stores ----
    float wsc = g_wscale * (1.0f / 127.0f);
#pragma unroll
    for (int mb = 0; mb < 4; mb++) {
        int r0 = m0 + wm * 64 + mb * 16 + g;
        float sc0 = wsc * g_ascale[r0];
        float sc1 = wsc * g_ascale[r0 + 8];
        float* o0 = out + (size_t)r0 * N_TOT + n0 + wn * 32 + q * 2;
        float* o1 = o0 + (size_t)8 * N_TOT;
#pragma unroll
        for (int nb = 0; nb < 4; nb++) {
            float2 v0, v1;
            v0.x = (float)acc[mb][nb][0] * sc0;
            v0.y = (float)acc[mb][nb][1] * sc0;
            v1.x = (float)acc[mb][nb][2] * sc1;
            v1.y = (float)acc[mb][nb][3] * sc1;
            *(float2*)(o0 + nb * 8) = v0;
            *(float2*)(o1 + nb * 8) = v1;
        }
    }
}

// ============================================================================
// Host launch
// ============================================================================
extern "C" void kernel_launch(void* const* d_in, const int* in_sizes, int n_in,
                              void* d_out, int out_size) {
    (void)in_sizes; (void)n_in; (void)out_size;
    const float* x = (const float*)d_in[0];
    const float* w = (const float*)d_in[1];
    float* out = (float*)d_out;

    cudaFuncSetAttribute(gemm_kernel, cudaFuncAttributeMaxDynamicSharedMemorySize,
                         SMEM_BYTES);

    wabs_kernel<<<1024, 256>>>(w);
    wquant_kernel<<<512, 256>>>(w);
    xquant_kernel<<<M_TOT / 2, 256>>>(x);
    gemm_kernel<<<(M_TOT / BM) * (N_TOT / BN), 256, SMEM_BYTES>>>(out);
}

// round 16
// speedup vs baseline: 1.2550x; 1.0512x over previous
#include <cuda_runtime.h>
#include <cuda_bf16.h>
#include <cstdint>

// ============================================================================
// BitLinear: y = (int8(x) @ ternary(W)^T) * (w_scale * a_scale / 127)
// Exact int8 IMMA (mma.sync m16n8k32 s8) GEMM, M=32768 N=1024 K=1024.
// Base sm_100 target: mma.sync + LDG only.  No tcgen05/TMA.
// R16: GEMM is SMEM-FREE and BARRIER-FREE.  Both A and B are stored in
//      per-lane mma fragment order by the quant kernels; the GEMM mainloop
//      is pure coalesced LDG + mma (no cp.async, no ldmatrix, no
//      __syncthreads).  8-bit B kept (R13-R15 showed decode ALU ops on the
//      mma critical path cost more than the L1 bytes they save).
// ============================================================================

#define EPS_F 1e-8f

static constexpr int M_TOT = 32768;
static constexpr int N_TOT = 1024;
static constexpr int K_TOT = 1024;

static constexpr int BM = 128, BN = 128;
static constexpr int KTILES = 16;                    // k-tiles of 64

// -------------------- device scratch (static; no allocations) ---------------
// A in mma-fragment order: [mgrp(2048)][kt(16)][ks(2)][lane(32)] -> uint4.
// lane l, mgrp g: x = A[g*16 + l/4      ][kt*64+ks*32+(l%4)*4 ..+3]
//                 y = A[g*16 + 8 + l/4  ][same k]
//                 z = x-row, k+16;  w = y-row, k+16.
// (exactly the m16n8k32 s8 A fragment {a0,a1,a2,a3})
__device__ uint4 g_afrag[(size_t)2048 * 1024];      // 32 MB
// B in mma-fragment order: [ngrp(128)][kt(16)][ks(2)][lane(32)] -> uint2.
// lane l: x = B[ngrp*8 + l/4][kt*64+ks*32+(l%4)*4 ..+3], y = same +16 bytes.
__device__ uint2 g_bfrag[128 * 16 * 2 * 32];        // 1 MB
__device__ float g_ascale[M_TOT];
__device__ float g_partial[1024];
__device__ float g_wscale;

// -------------------- PTX helpers -------------------------------------------
__device__ __forceinline__ void mma_s8(int* c, const uint32_t* a,
                                       uint32_t b0, uint32_t b1) {
    asm volatile(
        "mma.sync.aligned.m16n8k32.row.col.s32.s8.s8.s32 "
        "{%0,%1,%2,%3}, {%4,%5,%6,%7}, {%8,%9}, {%0,%1,%2,%3};"
        : "+r"(c[0]), "+r"(c[1]), "+r"(c[2]), "+r"(c[3])
        : "r"(a[0]), "r"(a[1]), "r"(a[2]), "r"(a[3]), "r"(b0), "r"(b1));
}

__device__ __forceinline__ uint32_t pack_q(float4 v, float inv) {
    int q0 = (int)rintf(fminf(fmaxf(v.x * inv, -128.0f), 127.0f));
    int q1 = (int)rintf(fminf(fmaxf(v.y * inv, -128.0f), 127.0f));
    int q2 = (int)rintf(fminf(fmaxf(v.z * inv, -128.0f), 127.0f));
    int q3 = (int)rintf(fminf(fmaxf(v.w * inv, -128.0f), 127.0f));
    return (uint32_t)(q0 & 0xFF) | ((uint32_t)(q1 & 0xFF) << 8)
         | ((uint32_t)(q2 & 0xFF) << 16) | ((uint32_t)(q3 & 0xFF) << 24);
}

// ============================================================================
// Kernel 1: per-block |W| partial sums (deterministic tree reduce)
// ============================================================================
__global__ void __launch_bounds__(256) wabs_kernel(const float* __restrict__ w) {
    __shared__ float sm[256];
    int t = threadIdx.x;
    size_t base = (size_t)blockIdx.x * 1024;
    float s = fabsf(w[base + t]) + fabsf(w[base + t + 256])
            + fabsf(w[base + t + 512]) + fabsf(w[base + t + 768]);
    sm[t] = s;
    __syncthreads();
    for (int o = 128; o > 0; o >>= 1) {
        if (t < o) sm[t] += sm[t + o];
        __syncthreads();
    }
    if (t == 0) g_partial[blockIdx.x] = sm[0];
}

// ============================================================================
// Kernel 2: ternary weight quant -> 8-bit B fragments (R11 layout).
// Each block re-derives w_scale from the 1024 partials (deterministic);
// block 0 publishes it.  One u32 scatter per thread.
// ============================================================================
__global__ void __launch_bounds__(256) wquant_kernel(const float* __restrict__ w) {
    __shared__ float sm[256];
    int t = threadIdx.x;
    float s = g_partial[t] + g_partial[t + 256] + g_partial[t + 512] + g_partial[t + 768];
    sm[t] = s;
    __syncthreads();
    for (int o = 128; o > 0; o >>= 1) {
        if (t < o) sm[t] += sm[t + o];
        __syncthreads();
    }
    float ws = sm[0] / 1048576.0f + EPS_F;
    if (blockIdx.x == 0 && t == 0) g_wscale = ws;

    int idx = (blockIdx.x * 256 + t) * 4;          // element index into W[n][k]
    float4 v = *(const float4*)(w + idx);
    float inv = 1.0f / ws;
    int q0 = (int)fminf(fmaxf(rintf(v.x * inv), -1.0f), 1.0f);
    int q1 = (int)fminf(fmaxf(rintf(v.y * inv), -1.0f), 1.0f);
    int q2 = (int)fminf(fmaxf(rintf(v.z * inv), -1.0f), 1.0f);
    int q3 = (int)fminf(fmaxf(rintf(v.w * inv), -1.0f), 1.0f);
    uint32_t p = (uint32_t)(q0 & 0xFF) | ((uint32_t)(q1 & 0xFF) << 8)
               | ((uint32_t)(q2 & 0xFF) << 16) | ((uint32_t)(q3 & 0xFF) << 24);

    int r = idx >> 10;                 // n row
    int k = idx & 1023;                // k of first element
    int kt = k >> 6;
    int ks = (k >> 5) & 1;
    int j  = (k >> 4) & 1;             // 0: .x, 1: .y
    int q  = (k >> 2) & 3;
    int lane = ((r & 7) << 2) | q;
    int ngrp = r >> 3;
    uint32_t* dst = (uint32_t*)&g_bfrag[((((ngrp * 16 + kt) * 2) + ks) << 5) + lane];
    dst[j] = p;
}

// ============================================================================
// Kernel 3: per-row activation quant -> A fragments.
// 512 threads = 16 warps = 16 rows (one mgrp).  Warp w owns row mgrp*16+w:
// per-lane max reduce, quantize, scatter into smem in fragment order, then
// one coalesced 16KB block write.
// ============================================================================
__global__ void __launch_bounds__(512) xquant_kernel(const float* __restrict__ x) {
    __shared__ uint32_t stg[4096];                  // 16 KB fragment image
    int t = threadIdx.x, w = t >> 5, lane = t & 31;
    int mgrp = blockIdx.x;
    int row = mgrp * 16 + w;
    const float4* xr = (const float4*)(x + (size_t)row * 1024);

    float4 v[8];
    float m = 0.0f;
#pragma unroll
    for (int i = 0; i < 8; i++) {
        v[i] = __ldcs(xr + lane + 32 * i);
        m = fmaxf(m, fmaxf(fmaxf(fabsf(v[i].x), fabsf(v[i].y)),
                           fmaxf(fabsf(v[i].z), fabsf(v[i].w))));
    }
#pragma unroll
    for (int o = 16; o; o >>= 1) m = fmaxf(m, __shfl_xor_sync(0xFFFFFFFFu, m, o));
    float s = m + EPS_F;
    if (lane == 0) g_ascale[row] = s;

    float inv = 127.0f / s;
    // fragment coordinates for this thread (f = lane + 32*i, k = 4f):
    //   kt = 2*i + (lane>>4), ks = (lane>>3)&1, j = (lane>>2)&1, q = lane&3
    int ks = (lane >> 3) & 1;
    int regidx = 2 * ((lane >> 2) & 1) + ((w >> 3) & 1);   // 2*j + (row-half)
    int lane_f = (w & 7) * 4 + (lane & 3);
#pragma unroll
    for (int i = 0; i < 8; i++) {
        int kt = 2 * i + (lane >> 4);
        stg[((kt * 2 + ks) * 32 + lane_f) * 4 + regidx] = pack_q(v[i], inv);
    }
    __syncthreads();

    // coalesced writeout: 1024 uint4 per mgrp
    uint4* dst = g_afrag + (size_t)mgrp * 1024;
    const uint4* src = (const uint4*)stg;
    dst[t] = src[t];
    dst[t + 512] = src[t + 512];
}

// ============================================================================
// Kernel 4: int8 IMMA GEMM — SMEM-free, barrier-free.
// 256 threads = 8 warps (2 m x 4 n), warp tile 64x32, CTA tile 128x128x64.
// Per warp-ktile: 8 LDG.64 (B frags) + 2x(4 LDG.128 A frags + 16 mma).
// ============================================================================
__global__ void __launch_bounds__(256, 2)
gemm_kernel(float* __restrict__ out) {
    int tid = threadIdx.x;
    int wid = tid >> 5, lane = tid & 31;
    int wm = wid >> 2, wn = wid & 3;           // 2 m x 4 n warp grid
    int g = lane >> 2, q = lane & 3;
    int m0 = (int)(blockIdx.x >> 3) * BM;
    int n0 = (int)(blockIdx.x & 7) * BN;

    // A fragment pointer: warp covers mgrps (m0/16 + wm*4) .. +3.
    // mgrp stride in uint4 = 16*2*32 = 1024.
    const uint4* awp = g_afrag + (size_t)((m0 >> 4) + wm * 4) * 1024 + lane;
    // B fragment pointer: warp covers ngrps (n0/8 + wn*4) .. +3.
    const uint2* bwp = g_bfrag + (size_t)((n0 >> 3) + wn * 4) * 1024 + lane;

    int acc[4][4][4];
#pragma unroll
    for (int i = 0; i < 4; i++)
#pragma unroll
        for (int j = 0; j < 4; j++)
#pragma unroll
            for (int r = 0; r < 4; r++) acc[i][j][r] = 0;

#pragma unroll 1
    for (int kt = 0; kt < KTILES; kt++) {
        // B fragments for the whole k-tile (L2-latency loads first)
        uint2 bv[8];
#pragma unroll
        for (int nb = 0; nb < 4; nb++) {
            bv[nb * 2 + 0] = __ldg(bwp + nb * 1024 + kt * 64);
            bv[nb * 2 + 1] = __ldg(bwp + nb * 1024 + kt * 64 + 32);
        }
#pragma unroll
        for (int ks = 0; ks < 2; ks++) {
            uint4 av[4];
#pragma unroll
            for (int mb = 0; mb < 4; mb++)
                av[mb] = __ldg(awp + mb * 1024 + kt * 64 + ks * 32);
#pragma unroll
            for (int mb = 0; mb < 4; mb++)
#pragma unroll
                for (int nb = 0; nb < 4; nb++)
                    mma_s8(acc[mb][nb], (const uint32_t*)&av[mb],
                           bv[nb * 2 + ks].x, bv[nb * 2 + ks].y);
        }
    }

    // ---- epilogue: dequant rescale + float2 stores ----
    float wsc = g_wscale * (1.0f / 127.0f);
#pragma unroll
    for (int mb = 0; mb < 4; mb++) {
        int r0 = m0 + wm * 64 + mb * 16 + g;
        float sc0 = wsc * g_ascale[r0];
        float sc1 = wsc * g_ascale[r0 + 8];
        float* o0 = out + (size_t)r0 * N_TOT + n0 + wn * 32 + q * 2;
        float* o1 = o0 + (size_t)8 * N_TOT;
#pragma unroll
        for (int nb = 0; nb < 4; nb++) {
            float2 v0, v1;
            v0.x = (float)acc[mb][nb][0] * sc0;
            v0.y = (float)acc[mb][nb][1] * sc0;
            v1.x = (float)acc[mb][nb][2] * sc1;
            v1.y = (float)acc[mb][nb][3] * sc1;
            *(float2*)(o0 + nb * 8) = v0;
            *(float2*)(o1 + nb * 8) = v1;
        }
    }
}

// ============================================================================
// Host launch
// ============================================================================
extern "C" void kernel_launch(void* const* d_in, const int* in_sizes, int n_in,
                              void* d_out, int out_size) {
    (void)in_sizes; (void)n_in; (void)out_size;
    const float* x = (const float*)d_in[0];
    const float* w = (const float*)d_in[1];
    float* out = (float*)d_out;

    wabs_kernel<<<1024, 256>>>(w);
    wquant_kernel<<<1024, 256>>>(w);
    xquant_kernel<<<M_TOT / 16, 512>>>(x);
    gemm_kernel<<<(M_TOT / BM) * (N_TOT / BN), 256>>>(out);
}